// round 1
// baseline (speedup 1.0000x reference)
#include <cuda_runtime.h>
#include <stdint.h>
#include <math.h>

#define T_FRAMES 64
#define H_DIM 1024
#define W_DIM 1024
#define NPIX (H_DIM * W_DIM)
#define TPB 256
#define ROWS_PER_BLOCK 16
#define CHUNKS (H_DIM / ROWS_PER_BLOCK)   // 64 blocks per frame
#define CAP 131072

// Ranks (0-based) of the order statistics, matching Python int() truncation
#define KG_RANK ((unsigned)((1.0 - 0.15) * (double)(NPIX - 1)))  // 891288
#define KB_RANK ((unsigned)((0.3) * (double)(NPIX - 1)))          // 314572

// ---------------- device scratch (static; no runtime allocation) ----------------
__device__ unsigned g_histG[T_FRAMES][4096];
__device__ unsigned g_histB[T_FRAMES][4096];
__device__ int4     g_sel[T_FRAMES];          // x=B1g, y=kg_rem, z=B1b, w=kb_rem
__device__ unsigned g_cntG[T_FRAMES];
__device__ unsigned g_cntB[T_FRAMES];
__device__ double   g_acc[T_FRAMES][4];       // cnt, sum(gm), sum(gm*x), sum(gm*y)
__device__ uint4    g_bufG[T_FRAMES][CAP];    // {gm2_key, bz_key, xy, 0}
__device__ uint4    g_bufB[T_FRAMES][CAP];    // {bz_key, gm2_key, xy, 0}

// ---------------- K0: zero scratch (graph replays need fresh state) -------------
__global__ void k_zero() {
    int i = blockIdx.x * blockDim.x + threadIdx.x;
    int total = T_FRAMES * 4096;
    if (i < total) {
        ((unsigned*)g_histG)[i] = 0;
        ((unsigned*)g_histB)[i] = 0;
    }
    if (i < T_FRAMES) {
        g_cntG[i] = 0;
        g_cntB[i] = 0;
        g_acc[i][0] = 0.0; g_acc[i][1] = 0.0; g_acc[i][2] = 0.0; g_acc[i][3] = 0.0;
    }
}

// ---------------- K1: top-12-bit histograms of gm2-keys and |f|-keys ------------
__global__ void __launch_bounds__(TPB) k_hist(const float* __restrict__ frames) {
    __shared__ unsigned hG[4096];
    __shared__ unsigned hB[4096];
    for (int i = threadIdx.x; i < 4096; i += TPB) { hG[i] = 0; hB[i] = 0; }
    __syncthreads();

    const int t = blockIdx.y;
    const float* __restrict__ f = frames + (size_t)t * NPIX;
    const int row0 = blockIdx.x * ROWS_PER_BLOCK;
    const int x0 = threadIdx.x * 4;
    const bool notLast = (threadIdx.x < TPB - 1);

    for (int r = 0; r < ROWS_PER_BLOCK; r++) {
        const int y = row0 + r;
        const int p = y * W_DIM + x0;
        float4 a = *(const float4*)(f + p);
        float rn = notLast ? f[p + 4] : 0.0f;
        const bool hasBelow = (y < H_DIM - 1);
        float4 b = hasBelow ? *(const float4*)(f + p + W_DIM) : make_float4(0.f, 0.f, 0.f, 0.f);
        float av[4] = {a.x, a.y, a.z, a.w};
        float bv[4] = {b.x, b.y, b.z, b.w};
        #pragma unroll
        for (int j = 0; j < 4; j++) {
            float gx = (j < 3) ? __fadd_rn(av[j + 1], -av[j])
                               : (notLast ? __fadd_rn(rn, -av[3]) : 0.0f);
            float gy = hasBelow ? __fadd_rn(bv[j], -av[j]) : 0.0f;
            // match XLA: mul, mul, add (no FMA contraction)
            float gm2 = __fadd_rn(__fmul_rn(gx, gx), __fmul_rn(gy, gy));
            unsigned kg = __float_as_uint(gm2);
            unsigned kb = __float_as_uint(fabsf(av[j]));
            atomicAdd(&hG[kg >> 20], 1u);
            atomicAdd(&hB[kb >> 20], 1u);
        }
    }
    __syncthreads();
    for (int i = threadIdx.x; i < 4096; i += TPB) {
        unsigned v = hG[i]; if (v) atomicAdd(&g_histG[t][i], v);
        v = hB[i];          if (v) atomicAdd(&g_histB[t][i], v);
    }
}

// ------------- generic "which bin holds rank K" over a shared histogram ---------
template <int NBINS>
__device__ __forceinline__ void kth_bin(unsigned* h, unsigned K, unsigned* toff,
                                        int* s_bin, unsigned* s_rem) {
    const int seg = NBINS / TPB;
    const int tid = threadIdx.x;
    unsigned s = 0;
    const int base = tid * seg;
    #pragma unroll
    for (int i = 0; i < seg; i++) s += h[base + i];
    toff[tid] = s;
    __syncthreads();
    if (tid == 0) {
        unsigned run = 0;
        for (int i = 0; i < TPB; i++) { unsigned v = toff[i]; toff[i] = run; run += v; }
    }
    __syncthreads();
    unsigned off = toff[tid];
    if (K >= off && K < off + s) {
        unsigned run = off;
        for (int i = 0; i < seg; i++) {
            unsigned c = h[base + i];
            if (K < run + c) { *s_bin = base + i; *s_rem = K - run; break; }
            run += c;
        }
    }
    __syncthreads();
}

// ---------------- K2: find candidate top bin + remainder rank per frame ---------
__global__ void __launch_bounds__(TPB) k_select() {
    __shared__ unsigned h[4096];
    __shared__ unsigned toff[TPB];
    __shared__ int s_bin;
    __shared__ unsigned s_rem;
    const int t = blockIdx.x;
    for (int which = 0; which < 2; which++) {
        const unsigned* src = which ? g_histB[t] : g_histG[t];
        const unsigned K = which ? KB_RANK : KG_RANK;
        for (int i = threadIdx.x; i < 4096; i += TPB) h[i] = src[i];
        __syncthreads();
        kth_bin<4096>(h, K, toff, &s_bin, &s_rem);
        if (threadIdx.x == 0) {
            if (which == 0) { g_sel[t].x = s_bin; g_sel[t].y = (int)s_rem; }
            else            { g_sel[t].z = s_bin; g_sel[t].w = (int)s_rem; }
        }
        __syncthreads();
    }
}

// --------------- warp-aggregated compaction append ------------------------------
__device__ __forceinline__ void warp_append(uint4* buf, unsigned* counter,
                                            bool pred, uint4 val) {
    unsigned m = __ballot_sync(0xffffffffu, pred);
    if (!m) return;
    int lane = threadIdx.x & 31;
    int leader = __ffs(m) - 1;
    unsigned base = 0;
    if (lane == leader) base = atomicAdd(counter, (unsigned)__popc(m));
    base = __shfl_sync(0xffffffffu, base, leader);
    if (pred) {
        unsigned idx = base + (unsigned)__popc(m & ((1u << lane) - 1u));
        if (idx < CAP) buf[idx] = val;
    }
}

// ---------------- K3: definite sums + compaction of ambiguous pixels ------------
__global__ void __launch_bounds__(TPB) k_sums(const float* __restrict__ frames) {
    const int t = blockIdx.y;
    const int4 sel = g_sel[t];
    const int B1g = sel.x, B1b = sel.z;
    const float* __restrict__ f = frames + (size_t)t * NPIX;
    const int row0 = blockIdx.x * ROWS_PER_BLOCK;
    const int x0 = threadIdx.x * 4;
    const bool notLast = (threadIdx.x < TPB - 1);

    int    cnt = 0;
    double sg = 0.0, sgx = 0.0, sgy = 0.0;
    double xd[4] = {(double)(x0), (double)(x0 + 1), (double)(x0 + 2), (double)(x0 + 3)};

    for (int r = 0; r < ROWS_PER_BLOCK; r++) {
        const int y = row0 + r;
        const double yd = (double)y;
        const int p = y * W_DIM + x0;
        float4 a = *(const float4*)(f + p);
        float rn = notLast ? f[p + 4] : 0.0f;
        const bool hasBelow = (y < H_DIM - 1);
        float4 b = hasBelow ? *(const float4*)(f + p + W_DIM) : make_float4(0.f, 0.f, 0.f, 0.f);
        float av[4] = {a.x, a.y, a.z, a.w};
        float bv[4] = {b.x, b.y, b.z, b.w};
        #pragma unroll
        for (int j = 0; j < 4; j++) {
            float gx = (j < 3) ? __fadd_rn(av[j + 1], -av[j])
                               : (notLast ? __fadd_rn(rn, -av[3]) : 0.0f);
            float gy = hasBelow ? __fadd_rn(bv[j], -av[j]) : 0.0f;
            float gm2 = __fadd_rn(__fmul_rn(gx, gx), __fmul_rn(gy, gy));
            unsigned kg = __float_as_uint(gm2);
            unsigned kb = __float_as_uint(fabsf(av[j]));
            int gbin = (int)(kg >> 20), bbin = (int)(kb >> 20);

            if (gbin >= B1g + 2 && bbin < B1b) {
                float gm = __fsqrt_rn(gm2);
                cnt += 1;
                sg  += (double)gm;
                sgx += (double)gm * xd[j];
                sgy += (double)gm * yd;
            }
            bool inG = (gbin == B1g) || (gbin == B1g + 1 && bbin <= B1b);
            bool inB = (bbin == B1b);
            unsigned xy = (unsigned)((y << 10) | (x0 + j));
            warp_append(g_bufG[t], &g_cntG[t], inG, make_uint4(kg, kb, xy, 0u));
            warp_append(g_bufB[t], &g_cntB[t], inB, make_uint4(kb, kg, xy, 0u));
        }
    }
    // warp reduce + atomic combine
    double dc = (double)cnt;
    #pragma unroll
    for (int o = 16; o; o >>= 1) {
        dc  += __shfl_down_sync(0xffffffffu, dc,  o);
        sg  += __shfl_down_sync(0xffffffffu, sg,  o);
        sgx += __shfl_down_sync(0xffffffffu, sgx, o);
        sgy += __shfl_down_sync(0xffffffffu, sgy, o);
    }
    if ((threadIdx.x & 31) == 0) {
        atomicAdd(&g_acc[t][0], dc);
        atomicAdd(&g_acc[t][1], sg);
        atomicAdd(&g_acc[t][2], sgx);
        atomicAdd(&g_acc[t][3], sgy);
    }
}

// ------- select exact low-20-bit key among compacted entries with given top bin --
__device__ unsigned select_in_buf(const uint4* buf, unsigned count, int topbin,
                                  unsigned krem, unsigned* h, unsigned* toff,
                                  int* s_bin, unsigned* s_rem) {
    const int tid = threadIdx.x;
    for (int i = tid; i < 4096; i += TPB) h[i] = 0;
    __syncthreads();
    for (unsigned i = tid; i < count; i += TPB) {
        unsigned k = buf[i].x;
        if ((int)(k >> 20) == topbin) atomicAdd(&h[(k >> 8) & 0xFFFu], 1u);
    }
    __syncthreads();
    kth_bin<4096>(h, krem, toff, s_bin, s_rem);
    int m = *s_bin;
    unsigned rem2 = *s_rem;
    __syncthreads();
    for (int i = tid; i < 256; i += TPB) h[i] = 0;
    __syncthreads();
    unsigned pref = ((unsigned)topbin << 12) | (unsigned)m;
    for (unsigned i = tid; i < count; i += TPB) {
        unsigned k = buf[i].x;
        if ((k >> 8) == pref) atomicAdd(&h[k & 0xFFu], 1u);
    }
    __syncthreads();
    kth_bin<256>(h, rem2, toff, s_bin, s_rem);
    unsigned key = (pref << 8) | (unsigned)(*s_bin);
    __syncthreads();
    return key;
}

// ---------------- K4: exact thresholds + resolve ambiguous pixels ----------------
__global__ void __launch_bounds__(TPB) k_resolve() {
    __shared__ unsigned h[4096];
    __shared__ unsigned toff[TPB];
    __shared__ int s_bin;
    __shared__ unsigned s_rem;
    __shared__ unsigned s_thrG;
    const int t = blockIdx.x;
    const int4 sel = g_sel[t];
    unsigned cG = min(g_cntG[t], (unsigned)CAP);
    unsigned cB = min(g_cntB[t], (unsigned)CAP);

    unsigned thr2 = select_in_buf(g_bufG[t], cG, sel.x, (unsigned)sel.y, h, toff, &s_bin, &s_rem);
    if (threadIdx.x == 0) {
        // widen to the largest key whose IEEE sqrt equals sqrt(thr2):
        // reference mask is sqrtf(gm2) > sqrtf(thr2)  <=>  key(gm2) > thr_eff
        float s = __fsqrt_rn(__uint_as_float(thr2));
        unsigned k = thr2;
        for (int i = 0; i < 64; i++) {
            if (__fsqrt_rn(__uint_as_float(k + 1u)) == s) k++;
            else break;
        }
        s_thrG = k;
    }
    unsigned thrB = select_in_buf(g_bufB[t], cB, sel.z, (unsigned)sel.w, h, toff, &s_bin, &s_rem);
    __syncthreads();
    const unsigned thrG = s_thrG;

    int    cnt = 0;
    double sg = 0.0, sgx = 0.0, sgy = 0.0;
    for (unsigned i = threadIdx.x; i < cG; i += TPB) {
        uint4 e = g_bufG[t][i];
        if (e.x > thrG && e.y < thrB) {
            float gm = __fsqrt_rn(__uint_as_float(e.x));
            cnt++;
            sg  += (double)gm;
            sgx += (double)gm * (double)(e.z & 1023u);
            sgy += (double)gm * (double)(e.z >> 10);
        }
    }
    for (unsigned i = threadIdx.x; i < cB; i += TPB) {
        uint4 e = g_bufB[t][i];
        if ((int)(e.y >> 20) > sel.x + 1 && e.x < thrB) {
            float gm = __fsqrt_rn(__uint_as_float(e.y));
            cnt++;
            sg  += (double)gm;
            sgx += (double)gm * (double)(e.z & 1023u);
            sgy += (double)gm * (double)(e.z >> 10);
        }
    }
    double dc = (double)cnt;
    #pragma unroll
    for (int o = 16; o; o >>= 1) {
        dc  += __shfl_down_sync(0xffffffffu, dc,  o);
        sg  += __shfl_down_sync(0xffffffffu, sg,  o);
        sgx += __shfl_down_sync(0xffffffffu, sgx, o);
        sgy += __shfl_down_sync(0xffffffffu, sgy, o);
    }
    if ((threadIdx.x & 31) == 0) {
        atomicAdd(&g_acc[t][0], dc);
        atomicAdd(&g_acc[t][1], sg);
        atomicAdd(&g_acc[t][2], sgx);
        atomicAdd(&g_acc[t][3], sgy);
    }
}

// ---------------- K5: depthwise conv + final 8 statistics ------------------------
__global__ void k_final(const float* __restrict__ conv_w,
                        const float* __restrict__ conv_b,
                        float* __restrict__ out) {
    if (threadIdx.x != 0 || blockIdx.x != 0) return;
    const int n = T_FRAMES;
    double st[T_FRAMES][4];
    for (int t = 0; t < n; t++) {
        double c = g_acc[t][0], sg = g_acc[t][1], sgx = g_acc[t][2], sgy = g_acc[t][3];
        double pil = c < 1e-6 ? 1e-6 : c;
        double ws  = sg < 1e-6 ? 1e-6 : sg;
        st[t][0] = c / (double)NPIX;
        st[t][1] = sg / pil;
        st[t][2] = sgx / ws / (double)W_DIM;
        st[t][3] = sgy / ws / (double)H_DIM;
    }
    double y[T_FRAMES][4];
    for (int t = 0; t < n; t++) {
        for (int c = 0; c < 4; c++) {
            double v = (double)conv_b[c] + (double)conv_w[c * 3 + 1] * st[t][c];
            if (t > 0)     v += (double)conv_w[c * 3 + 0] * st[t - 1][c];
            if (t < n - 1) v += (double)conv_w[c * 3 + 2] * st[t + 1][c];
            y[t][c] = v;
        }
    }
    double lm = 0.0, im = 0.0;
    for (int t = 0; t < n; t++) { lm += y[t][0]; im += y[t][1]; }
    lm /= n; im /= n;
    double lt = 0.0, itr = 0.0;
    for (int t = 0; t < n; t++) {
        double tn = (double)t / (double)(n - 1) - 0.5;
        lt  += (y[t][0] - lm) * tn;
        itr += (y[t][1] - im) * tn;
    }
    lt  *= 6.0 / (double)n;
    itr *= 6.0 / (double)n;
    double sdx = 0.0, sdy = 0.0, ssum = 0.0, sp[T_FRAMES - 1];
    for (int t = 0; t < n - 1; t++) {
        double dx = y[t + 1][2] - y[t][2];
        double dy = y[t + 1][3] - y[t][3];
        sp[t] = sqrt(dx * dx + dy * dy);
        sdx += dx; sdy += dy; ssum += sp[t];
    }
    double ms = ssum / (double)(n - 1);
    double md = atan2(sdy, sdx) / 3.14159265358979323846;
    double gr = (y[n - 1][0] - y[0][0]) / (double)(n - 1);
    double var = 0.0;
    for (int t = 0; t < n - 1; t++) { double d = sp[t] - ms; var += d * d; }
    var /= (double)(n - 2);
    double inst = sqrt(var);

    out[0] = (float)lm;
    out[1] = (float)lt;
    out[2] = (float)im;
    out[3] = (float)itr;
    out[4] = (float)ms;
    out[5] = (float)md;
    out[6] = (float)gr;
    out[7] = (float)inst;
}

// ---------------- entry point -----------------------------------------------------
extern "C" void kernel_launch(void* const* d_in, const int* in_sizes, int n_in,
                              void* d_out, int out_size) {
    const float* frames = (const float*)d_in[0];
    // d_in[1] = observed_mask (unused by reference)
    const float* conv_w = (const float*)d_in[2];
    const float* conv_b = (const float*)d_in[3];
    float* out = (float*)d_out;

    k_zero<<<(T_FRAMES * 4096 + TPB - 1) / TPB, TPB>>>();
    dim3 grid(CHUNKS, T_FRAMES);
    k_hist<<<grid, TPB>>>(frames);
    k_select<<<T_FRAMES, TPB>>>();
    k_sums<<<grid, TPB>>>(frames);
    k_resolve<<<T_FRAMES, TPB>>>();
    k_final<<<1, 32>>>(conv_w, conv_b, out);
}